// round 8
// baseline (speedup 1.0000x reference)
#include <cuda_runtime.h>
#include <cuda_fp16.h>

// Problem constants
#define CC   256
#define CR   64
#define HH   56
#define WW   56
#define BB   4
#define GG   16
#define CGC  16
#define KK   7
#define NPIX (HH*WW)     // 3136
#define NQ   (BB*NPIX)   // 12544

// Bottleneck activations, channel-pair-major: t2_buf[c2*NQ + q] = (t[2c2], t[2c2+1])
__device__ unsigned long long t2_buf[32 * NQ];

// ---------------- packed f32x2 helpers ----------------
__device__ __forceinline__ unsigned long long ffma2(unsigned long long a,
                                                    unsigned long long b,
                                                    unsigned long long c) {
    unsigned long long d;
    asm("fma.rn.f32x2 %0, %1, %2, %3;" : "=l"(d) : "l"(a), "l"(b), "l"(c));
    return d;
}
__device__ __forceinline__ float2 u2f(unsigned long long v) {
    float2 r;
    asm("mov.b64 {%0,%1}, %2;" : "=f"(r.x), "=f"(r.y) : "l"(v));
    return r;
}
__device__ __forceinline__ unsigned long long f2u(float x, float y) {
    unsigned long long v;
    asm("mov.b64 %0, {%1,%2};" : "=l"(v) : "f"(x), "f"(y));
    return v;
}

// =====================================================================
// Kernel 1: t = relu(BN(x @ W1^T + b1)) -> t2_buf[c2][q]
// Grid 392 x 128 threads. tid = oq(0..3)*32 + lane. 1 pixel per thread,
// 16 outputs. W1 transposed in smem, broadcast LDS.128 per warp.
// smem 68.5 KB -> 3 CTAs/SM; grid/148 = 2.65 -> ~10.6 warps/SM.
// =====================================================================
#define W1T_STRIDE 68   // floats; keeps (c,o0) float4 16B-aligned, spreads banks

extern "C" __global__ void __launch_bounds__(128)
k1_gen_t(const float* __restrict__ x, const float* __restrict__ W1,
         const float* __restrict__ b1, const float* __restrict__ gamma,
         const float* __restrict__ beta, const float* __restrict__ mean,
         const float* __restrict__ var)
{
    extern __shared__ float sm1[];
    float* w1T = sm1;                         // [256][68]
    float* sc  = sm1 + CC * W1T_STRIDE;       // [64]
    float* sh  = sc + CR;                     // [64]

    int tid = threadIdx.x;

    for (int i = tid; i < CR * CC; i += 128) {
        int o = i >> 8;
        int c = i & 255;
        w1T[c * W1T_STRIDE + o] = W1[i];
    }
    if (tid < CR) {
        float s = gamma[tid] * rsqrtf(var[tid] + 1e-5f);
        sc[tid] = s;
        sh[tid] = (b1[tid] - mean[tid]) * s + beta[tid];
    }
    __syncthreads();

    int lane = tid & 31;
    int oq   = tid >> 5;                 // 0..3
    int o0   = oq * 16;
    int q    = blockIdx.x * 32 + lane;   // 32 | NPIX -> same batch per CTA
    int b    = (blockIdx.x * 32) / NPIX;
    int hw   = q - b * NPIX;
    const float* xp = x + (size_t)b * (CC * NPIX) + hw;

    unsigned long long acc[8];
    #pragma unroll
    for (int m = 0; m < 8; m++) acc[m] = 0ull;

    #pragma unroll 4
    for (int c = 0; c < CC; c++) {
        float xv = xp[c * NPIX];                       // coalesced 128B
        unsigned long long xx = f2u(xv, xv);
        const float4* w4 = (const float4*)(w1T + c * W1T_STRIDE + o0);
        #pragma unroll
        for (int m = 0; m < 4; m++) {
            float4 w = w4[m];                          // broadcast LDS.128 (1 wf)
            acc[2*m]   = ffma2(xx, f2u(w.x, w.y), acc[2*m]);
            acc[2*m+1] = ffma2(xx, f2u(w.z, w.w), acc[2*m+1]);
        }
    }

    #pragma unroll
    for (int m = 0; m < 8; m++) {
        int o  = o0 + 2 * m;
        int c2 = oq * 8 + m;
        float2 v = u2f(acc[m]);
        float a0 = fmaxf(v.x * sc[o]   + sh[o],   0.f);
        float a1 = fmaxf(v.y * sc[o+1] + sh[o+1], 0.f);
        t2_buf[(size_t)c2 * NQ + q] = f2u(a0, a1);     // coalesced 256B
    }
}

// =====================================================================
// Kernel 2 (fused): per-pixel kernel gen (GEMM2) + involution.
// Grid (10, 16, 4), 192 threads, __launch_bounds__(192,2) -> 2 CTAs/SM.
// CTA tile = 6 rows x 56 cols. Worker (tid<168, row in range) owns 2
// vertically adjacent pixels. W2 LDS.128 broadcasts amortized over both
// pixels; x tap rows shared between the pair. Per-pixel weights staged
// in fp16 smem (stride 50 halves -> conflict-free).
// smem ~91.8 KB -> 2 CTAs/SM.
// =====================================================================
#define RPC  6               // rows per CTA
#define XT_W 62              // 56 + 6
#define XT_H 12              // 6  + 6
#define XT_CH (XT_H * XT_W)  // 744 float2 per channel-pair
#define WS_STRIDE 50         // halves per weight slot (49 used)

extern "C" __global__ void __launch_bounds__(192, 2)
k2_inv(const float* __restrict__ x, const float* __restrict__ W2,
       const float* __restrict__ b2, float* __restrict__ out)
{
    extern __shared__ float sm2[];
    float2* xs2 = (float2*)sm2;                    // [8][12][62] float2 = 47.6 KB
    float*  w2s = sm2 + 2 * 8 * XT_CH;             // [49][64] = 12.5 KB
    float*  b2s = w2s + 49 * CR;                   // [64]
    __half* ws  = (__half*)(b2s + 64);             // [336][50] half = 33.6 KB

    int tid = threadIdx.x;
    int r0  = blockIdx.x * RPC;
    int g   = blockIdx.y;
    int b   = blockIdx.z;

    // ---- cooperative fills ----
    const float* xg = x + (size_t)((b * GG + g) * CGC) * NPIX;
    for (int i = tid; i < 8 * XT_CH; i += 192) {
        int cp  = i / XT_CH;
        int rem = i - cp * XT_CH;
        int ri  = rem / XT_W;
        int ci  = rem - ri * XT_W;
        int gr  = r0 - 3 + ri;
        int gc  = ci - 3;
        float v0 = 0.f, v1 = 0.f;
        if ((unsigned)gr < HH && (unsigned)gc < WW) {
            int off = gr * WW + gc;
            v0 = xg[cp * NPIX + off];
            v1 = xg[(cp + 8) * NPIX + off];
        }
        xs2[i] = make_float2(v0, v1);
    }
    for (int i = tid; i < 49 * CR; i += 192)
        w2s[i] = W2[(size_t)g * 49 * CR + i];
    if (tid < 49) b2s[tid] = b2[g * 49 + tid];

    // ---- per-thread t vectors for both pixels (registers) ----
    int rl = tid / 56;                 // 0..2 (3 for tail threads)
    int cl = tid - rl * 56;
    int rA = r0 + 2 * rl;
    bool act = (tid < 168) && (rA < HH);

    unsigned long long ttA[32], ttB[32];
    if (act) {
        int qA = b * NPIX + rA * WW + cl;
        #pragma unroll
        for (int c2 = 0; c2 < 32; c2++) {
            ttA[c2] = t2_buf[(size_t)c2 * NQ + qA];
            ttB[c2] = t2_buf[(size_t)c2 * NQ + qA + WW];
        }
    }
    __syncthreads();
    if (!act) return;

    // ---- kernel generation: w[p][k] = t[p].W2[g,k] + b2, both pixels ----
    __half* wsA = ws + tid * WS_STRIDE;
    __half* wsB = ws + (168 + tid) * WS_STRIDE;
    for (int k = 0; k < 49; k++) {
        const float4* w4 = (const float4*)(w2s + (k << 6));
        unsigned long long aA0 = 0ull, aA1 = 0ull, aB0 = 0ull, aB1 = 0ull;
        #pragma unroll
        for (int m = 0; m < 16; m++) {
            float4 w = w4[m];                          // broadcast LDS.128 (1 wf)
            unsigned long long w01 = f2u(w.x, w.y);
            unsigned long long w23 = f2u(w.z, w.w);
            aA0 = ffma2(ttA[2*m],   w01, aA0);
            aA1 = ffma2(ttA[2*m+1], w23, aA1);
            aB0 = ffma2(ttB[2*m],   w01, aB0);
            aB1 = ffma2(ttB[2*m+1], w23, aB1);
        }
        float bias = b2s[k];
        float2 uA0 = u2f(aA0), uA1 = u2f(aA1);
        wsA[k] = __float2half(uA0.x + uA0.y + uA1.x + uA1.y + bias);
        float2 uB0 = u2f(aB0), uB1 = u2f(aB1);
        wsB[k] = __float2half(uB0.x + uB0.y + uB1.x + uB1.y + bias);
    }
    __syncwarp();

    // ---- involution: both pixels share the 8-row window ----
    unsigned long long oA[8], oB[8];
    #pragma unroll
    for (int cp = 0; cp < 8; cp++) { oA[cp] = 0ull; oB[cp] = 0ull; }

    const float2* xb0 = xs2 + (2 * rl) * XT_W + cl;

    // t = 0: pixel A only (tap row 0)
    #pragma unroll
    for (int j = 0; j < KK; j++) {
        float wa = __half2float(wsA[j]);
        unsigned long long wa2 = f2u(wa, wa);
        #pragma unroll
        for (int cp = 0; cp < 8; cp++) {
            unsigned long long xv = *(const unsigned long long*)(xb0 + cp * XT_CH + j);
            oA[cp] = ffma2(xv, wa2, oA[cp]);
        }
    }
    // t = 1..6: both pixels share x
    for (int t = 1; t <= 6; t++) {
        const float2* xbt = xb0 + t * XT_W;
        const __half* wra = wsA + t * KK;
        const __half* wrb = wsB + (t - 1) * KK;
        #pragma unroll
        for (int j = 0; j < KK; j++) {
            float wa = __half2float(wra[j]);
            float wb = __half2float(wrb[j]);
            unsigned long long wa2 = f2u(wa, wa);
            unsigned long long wb2 = f2u(wb, wb);
            #pragma unroll
            for (int cp = 0; cp < 8; cp++) {
                unsigned long long xv = *(const unsigned long long*)(xbt + cp * XT_CH + j);
                oA[cp] = ffma2(xv, wa2, oA[cp]);
                oB[cp] = ffma2(xv, wb2, oB[cp]);
            }
        }
    }
    // t = 7: pixel B only (tap row 6)
    {
        const float2* xbt = xb0 + 7 * XT_W;
        #pragma unroll
        for (int j = 0; j < KK; j++) {
            float wb = __half2float(wsB[42 + j]);
            unsigned long long wb2 = f2u(wb, wb);
            #pragma unroll
            for (int cp = 0; cp < 8; cp++) {
                unsigned long long xv = *(const unsigned long long*)(xbt + cp * XT_CH + j);
                oB[cp] = ffma2(xv, wb2, oB[cp]);
            }
        }
    }

    // ---- store ----
    float* op = out + (size_t)(b * CC + g * CGC) * NPIX + rA * WW + cl;
    #pragma unroll
    for (int cp = 0; cp < 8; cp++) {
        float2 vA = u2f(oA[cp]);
        float2 vB = u2f(oB[cp]);
        op[cp * NPIX]            = vA.x;
        op[(cp + 8) * NPIX]      = vA.y;
        op[cp * NPIX + WW]       = vB.x;
        op[(cp + 8) * NPIX + WW] = vB.y;
    }
}

// =====================================================================
// Launch
// =====================================================================
extern "C" void kernel_launch(void* const* d_in, const int* in_sizes, int n_in,
                              void* d_out, int out_size) {
    const float* x     = (const float*)d_in[0];
    const float* W1    = (const float*)d_in[1];
    const float* b1    = (const float*)d_in[2];
    const float* gamma = (const float*)d_in[3];
    const float* beta  = (const float*)d_in[4];
    const float* mean  = (const float*)d_in[5];
    const float* var   = (const float*)d_in[6];
    const float* W2    = (const float*)d_in[7];
    const float* b2    = (const float*)d_in[8];
    float* out = (float*)d_out;

    const int smem1 = (CC * W1T_STRIDE + 2 * CR) * sizeof(float);   // ~68.5 KB
    const int smem2 = (2 * 8 * XT_CH + 49 * CR + 64) * sizeof(float)
                    + 336 * WS_STRIDE * sizeof(__half);             // ~92 KB

    (void)cudaFuncSetAttribute(k1_gen_t, cudaFuncAttributeMaxDynamicSharedMemorySize, smem1);
    (void)cudaFuncSetAttribute(k2_inv,   cudaFuncAttributeMaxDynamicSharedMemorySize, smem2);

    k1_gen_t<<<NQ / 32, 128, smem1>>>(x, W1, b1, gamma, beta, mean, var);
    k2_inv<<<dim3((HH + RPC - 1) / RPC, GG, BB), 192, smem2>>>(x, W2, b2, out);
}

// round 9
// speedup vs baseline: 1.1478x; 1.1478x over previous
#include <cuda_runtime.h>
#include <cuda_fp16.h>

// Problem constants
#define CC   256
#define CR   64
#define HH   56
#define WW   56
#define BB   4
#define GG   16
#define CGC  16
#define KK   7
#define NPIX (HH*WW)     // 3136
#define NQ   (BB*NPIX)   // 12544
#define NN   (GG*KK*KK)  // 784

// Intermediates
__device__ float  t_lin[CR * NQ];   // t, channel-major [c][q], 3.2 MB
__device__ __half w_h[NN * NQ];     // per-pixel kernels, [n][q], fp16, 19.7 MB

// ---------------- packed f32x2 helpers ----------------
__device__ __forceinline__ unsigned long long ffma2(unsigned long long a,
                                                    unsigned long long b,
                                                    unsigned long long c) {
    unsigned long long d;
    asm("fma.rn.f32x2 %0, %1, %2, %3;" : "=l"(d) : "l"(a), "l"(b), "l"(c));
    return d;
}
__device__ __forceinline__ float2 u2f(unsigned long long v) {
    float2 r;
    asm("mov.b64 {%0,%1}, %2;" : "=f"(r.x), "=f"(r.y) : "l"(v));
    return r;
}
__device__ __forceinline__ unsigned long long f2u(float x, float y) {
    unsigned long long v;
    asm("mov.b64 %0, {%1,%2};" : "=l"(v) : "f"(x), "f"(y));
    return v;
}
__device__ __forceinline__ unsigned h2_as_u(__half2 h) {
    unsigned u;
    asm("mov.b32 %0, %1;" : "=r"(u) : "r"(*(unsigned*)&h));
    return u;
}

// =====================================================================
// Kernel 1: t = relu(BN(x @ W1^T + b1)) -> t_lin[c][q]
// Grid 392 x 128. Thread: 1 pixel, 16 outputs (og = tid>>5).
// =====================================================================
#define W1T_STRIDE 68

extern "C" __global__ void __launch_bounds__(128)
k1_gen_t(const float* __restrict__ x, const float* __restrict__ W1,
         const float* __restrict__ b1, const float* __restrict__ gamma,
         const float* __restrict__ beta, const float* __restrict__ mean,
         const float* __restrict__ var)
{
    extern __shared__ float sm1[];
    float* w1T = sm1;                         // [256][68]
    float* sc  = sm1 + CC * W1T_STRIDE;       // [64]
    float* sh  = sc + CR;                     // [64]

    int tid = threadIdx.x;
    for (int i = tid; i < CR * CC; i += 128) {
        int o = i >> 8;
        int c = i & 255;
        w1T[c * W1T_STRIDE + o] = W1[i];
    }
    if (tid < CR) {
        float s = gamma[tid] * rsqrtf(var[tid] + 1e-5f);
        sc[tid] = s;
        sh[tid] = (b1[tid] - mean[tid]) * s + beta[tid];
    }
    __syncthreads();

    int lane = tid & 31;
    int og   = tid >> 5;                 // 0..3
    int o0   = og * 16;
    int q    = blockIdx.x * 32 + lane;
    int b    = (blockIdx.x * 32) / NPIX; // 32 | NPIX
    int hw   = q - b * NPIX;
    const float* xp = x + (size_t)b * (CC * NPIX) + hw;

    unsigned long long acc[8];
    #pragma unroll
    for (int m = 0; m < 8; m++) acc[m] = 0ull;

    #pragma unroll 4
    for (int c = 0; c < CC; c++) {
        float xv = xp[c * NPIX];
        unsigned long long xx = f2u(xv, xv);
        const float4* w4 = (const float4*)(w1T + c * W1T_STRIDE + o0);
        #pragma unroll
        for (int m = 0; m < 4; m++) {
            float4 w = w4[m];                       // broadcast LDS.128
            acc[2*m]   = ffma2(xx, f2u(w.x, w.y), acc[2*m]);
            acc[2*m+1] = ffma2(xx, f2u(w.z, w.w), acc[2*m+1]);
        }
    }

    #pragma unroll
    for (int m = 0; m < 8; m++) {
        int o = o0 + 2 * m;
        float2 v = u2f(acc[m]);
        t_lin[(size_t)o * NQ + q]       = fmaxf(v.x * sc[o]   + sh[o],   0.f);
        t_lin[(size_t)(o + 1) * NQ + q] = fmaxf(v.y * sc[o+1] + sh[o+1], 0.f);
    }
}

// =====================================================================
// Kernel 2: w-gen GEMM. C[n][q] = sum_c W2[n][c] * t[c][q] + b2[n].
// M(n)=784 (padded 832), N(q)=12544, K(c)=64.
// Grid (98 q-tiles, 13 n-tiles), 256 threads.
// CTA tile 64n x 128q; thread tile 8n x 4q (f32x2 over n-pairs).
// =====================================================================
#define QT 128
#define NT 64
#define TS_STRIDE  132   // floats, padded (avoids STS same-bank)
#define W2T_STRIDE 68

extern "C" __global__ void __launch_bounds__(256)
k2_wgen(const float* __restrict__ W2, const float* __restrict__ b2)
{
    extern __shared__ float smg[];
    float* ts  = smg;                        // [64][132]
    float* w2T = smg + 64 * TS_STRIDE;       // [64][68]  (c-major, n fast)

    int tid = threadIdx.x;
    int q0  = blockIdx.x * QT;
    int nb  = blockIdx.y * NT;

    // load t tile [64c][128q] via float4 (global coalesced)
    #pragma unroll
    for (int k = 0; k < 8; k++) {
        int li = tid + k * 256;              // 0..2047
        int c  = li >> 5;
        int q4 = li & 31;
        float4 v = *(const float4*)(t_lin + (size_t)c * NQ + q0 + q4 * 4);
        *(float4*)(ts + c * TS_STRIDE + q4 * 4) = v;
    }
    // load W2 tile transposed -> w2T[c][n_loc], zero-pad n >= 784
    #pragma unroll
    for (int k = 0; k < 16; k++) {
        int li    = tid + k * 256;           // 0..4095
        int n_loc = li >> 6;
        int c     = li & 63;
        int n     = nb + n_loc;
        float v   = (n < NN) ? W2[(size_t)n * CR + c] : 0.f;
        w2T[c * W2T_STRIDE + n_loc] = v;
    }
    __syncthreads();

    int qs = tid & 31;       // q slot: 4 q's
    int ns = tid >> 5;       // n slot: 8 n's
    int n0 = ns * 8;

    unsigned long long acc[4][4];            // [n-pair][q]
    #pragma unroll
    for (int i = 0; i < 4; i++)
        #pragma unroll
        for (int j = 0; j < 4; j++) acc[i][j] = 0ull;

    #pragma unroll 4
    for (int c = 0; c < CR; c++) {
        float4 tq = *(const float4*)(ts + c * TS_STRIDE + qs * 4);
        float4 wa = *(const float4*)(w2T + c * W2T_STRIDE + n0);
        float4 wb = *(const float4*)(w2T + c * W2T_STRIDE + n0 + 4);
        unsigned long long t0 = f2u(tq.x, tq.x), t1 = f2u(tq.y, tq.y);
        unsigned long long t2 = f2u(tq.z, tq.z), t3 = f2u(tq.w, tq.w);
        unsigned long long w01 = f2u(wa.x, wa.y), w23 = f2u(wa.z, wa.w);
        unsigned long long w45 = f2u(wb.x, wb.y), w67 = f2u(wb.z, wb.w);
        acc[0][0] = ffma2(w01, t0, acc[0][0]);
        acc[0][1] = ffma2(w01, t1, acc[0][1]);
        acc[0][2] = ffma2(w01, t2, acc[0][2]);
        acc[0][3] = ffma2(w01, t3, acc[0][3]);
        acc[1][0] = ffma2(w23, t0, acc[1][0]);
        acc[1][1] = ffma2(w23, t1, acc[1][1]);
        acc[1][2] = ffma2(w23, t2, acc[1][2]);
        acc[1][3] = ffma2(w23, t3, acc[1][3]);
        acc[2][0] = ffma2(w45, t0, acc[2][0]);
        acc[2][1] = ffma2(w45, t1, acc[2][1]);
        acc[2][2] = ffma2(w45, t2, acc[2][2]);
        acc[2][3] = ffma2(w45, t3, acc[2][3]);
        acc[3][0] = ffma2(w67, t0, acc[3][0]);
        acc[3][1] = ffma2(w67, t1, acc[3][1]);
        acc[3][2] = ffma2(w67, t2, acc[3][2]);
        acc[3][3] = ffma2(w67, t3, acc[3][3]);
    }

    // epilogue: bias + fp16 store, layout [n][q]
    #pragma unroll
    for (int np = 0; np < 4; np++) {
        int n_a = nb + n0 + 2 * np;
        int n_b = n_a + 1;
        float ba = (n_a < NN) ? b2[n_a] : 0.f;
        float bb = (n_b < NN) ? b2[n_b] : 0.f;
        float2 v0 = u2f(acc[np][0]), v1 = u2f(acc[np][1]);
        float2 v2 = u2f(acc[np][2]), v3 = u2f(acc[np][3]);
        if (n_a < NN) {
            __half2 h01 = __floats2half2_rn(v0.x + ba, v1.x + ba);
            __half2 h23 = __floats2half2_rn(v2.x + ba, v3.x + ba);
            unsigned long long pk =
                ((unsigned long long)h2_as_u(h23) << 32) | h2_as_u(h01);
            *(unsigned long long*)(w_h + (size_t)n_a * NQ + q0 + qs * 4) = pk;
        }
        if (n_b < NN) {
            __half2 h01 = __floats2half2_rn(v0.y + bb, v1.y + bb);
            __half2 h23 = __floats2half2_rn(v2.y + bb, v3.y + bb);
            unsigned long long pk =
                ((unsigned long long)h2_as_u(h23) << 32) | h2_as_u(h01);
            *(unsigned long long*)(w_h + (size_t)n_b * NQ + q0 + qs * 4) = pk;
        }
    }
}

// =====================================================================
// Kernel 3: involution. Grid (7, 16, 4), 224 threads. CTA = 8 rows x 56.
// Thread owns 2 vertically adjacent pixels (row-pair), reads its 98 tap
// weights from w_h (coalesced across lanes), x from smem channel-pair tile.
// =====================================================================
#define XT_W 62              // 56 + 6
#define XT_H 14              // 8 + 6
#define XT_CH (XT_H * XT_W)  // 868 float2 per channel-pair

extern "C" __global__ void __launch_bounds__(224)
k3_inv(const float* __restrict__ x, float* __restrict__ out)
{
    extern __shared__ float sm3[];
    float2* xs2 = (float2*)sm3;              // [8][14][62] float2 = 55.5 KB

    int tid = threadIdx.x;
    int r0  = blockIdx.x * 8;
    int g   = blockIdx.y;
    int b   = blockIdx.z;

    const float* xg = x + (size_t)((b * GG + g) * CGC) * NPIX;
    for (int i = tid; i < 8 * XT_CH; i += 224) {
        int cp  = i / XT_CH;
        int rem = i - cp * XT_CH;
        int ri  = rem / XT_W;
        int ci  = rem - ri * XT_W;
        int gr  = r0 - 3 + ri;
        int gc  = ci - 3;
        float v0 = 0.f, v1 = 0.f;
        if ((unsigned)gr < HH && (unsigned)gc < WW) {
            int off = gr * WW + gc;
            v0 = xg[cp * NPIX + off];
            v1 = xg[(cp + 8) * NPIX + off];
        }
        xs2[i] = make_float2(v0, v1);
    }
    __syncthreads();

    int rl = tid / 56;                   // 0..3 (row-pair)
    int cl = tid - rl * 56;
    int rA = r0 + 2 * rl;
    int qA = b * NPIX + rA * WW + cl;

    const __half* wg = w_h + (size_t)(g * 49) * NQ + qA;  // [k][.] at stride NQ

    unsigned long long oA[8], oB[8];
    #pragma unroll
    for (int cp = 0; cp < 8; cp++) { oA[cp] = 0ull; oB[cp] = 0ull; }

    const float2* xb0 = xs2 + (2 * rl) * XT_W + cl;

    #pragma unroll
    for (int t = 0; t < 8; t++) {
        // weights: px A uses tap-row t (if t<7), px B uses tap-row t-1 (if t>=1)
        unsigned long long wa2[7], wb2[7];
        if (t < 7) {
            #pragma unroll
            for (int j = 0; j < 7; j++) {
                float w = __half2float(wg[(size_t)(t * 7 + j) * NQ]);
                wa2[j] = f2u(w, w);
            }
        }
        if (t >= 1) {
            #pragma unroll
            for (int j = 0; j < 7; j++) {
                float w = __half2float(wg[(size_t)((t - 1) * 7 + j) * NQ + WW]);
                wb2[j] = f2u(w, w);
            }
        }
        const float2* xr = xb0 + t * XT_W;
        #pragma unroll
        for (int j = 0; j < 7; j++) {
            #pragma unroll
            for (int cp = 0; cp < 8; cp++) {
                unsigned long long xv =
                    *(const unsigned long long*)(xr + cp * XT_CH + j);
                if (t < 7)  oA[cp] = ffma2(xv, wa2[j], oA[cp]);
                if (t >= 1) oB[cp] = ffma2(xv, wb2[j], oB[cp]);
            }
        }
    }

    float* op = out + (size_t)(b * CC + g * CGC) * NPIX + rA * WW + cl;
    #pragma unroll
    for (int cp = 0; cp < 8; cp++) {
        float2 vA = u2f(oA[cp]);
        float2 vB = u2f(oB[cp]);
        op[cp * NPIX]            = vA.x;
        op[(cp + 8) * NPIX]      = vA.y;
        op[cp * NPIX + WW]       = vB.x;
        op[(cp + 8) * NPIX + WW] = vB.y;
    }
}

// =====================================================================
// Launch
// =====================================================================
extern "C" void kernel_launch(void* const* d_in, const int* in_sizes, int n_in,
                              void* d_out, int out_size) {
    const float* x     = (const float*)d_in[0];
    const float* W1    = (const float*)d_in[1];
    const float* b1    = (const float*)d_in[2];
    const float* gamma = (const float*)d_in[3];
    const float* beta  = (const float*)d_in[4];
    const float* mean  = (const float*)d_in[5];
    const float* var   = (const float*)d_in[6];
    const float* W2    = (const float*)d_in[7];
    const float* b2    = (const float*)d_in[8];
    float* out = (float*)d_out;

    const int smem1 = (CC * W1T_STRIDE + 2 * CR) * sizeof(float);       // ~68.5 KB
    const int smem2 = (64 * TS_STRIDE + 64 * W2T_STRIDE) * sizeof(float); // 51.2 KB
    const int smem3 = 8 * XT_CH * sizeof(float2);                        // 55.5 KB

    (void)cudaFuncSetAttribute(k1_gen_t, cudaFuncAttributeMaxDynamicSharedMemorySize, smem1);
    (void)cudaFuncSetAttribute(k2_wgen,  cudaFuncAttributeMaxDynamicSharedMemorySize, smem2);
    (void)cudaFuncSetAttribute(k3_inv,   cudaFuncAttributeMaxDynamicSharedMemorySize, smem3);

    k1_gen_t<<<NQ / 32, 128, smem1>>>(x, W1, b1, gamma, beta, mean, var);
    k2_wgen<<<dim3(NQ / QT, (NN + NT - 1) / NT), 256, smem2>>>(W2, b2);
    k3_inv<<<dim3(HH / 8, GG, BB), 224, smem3>>>(x, out);
}

// round 10
// speedup vs baseline: 1.2686x; 1.1053x over previous
#include <cuda_runtime.h>
#include <cuda_fp16.h>

// Problem constants
#define CC   256
#define CR   64
#define HH   56
#define WW   56
#define BB   4
#define GG   16
#define CGC  16
#define KK   7
#define NPIX (HH*WW)     // 3136
#define NQ   (BB*NPIX)   // 12544
#define NN   (GG*KK*KK)  // 784

// Intermediates
__device__ float  t_lin[CR * NQ];   // t, channel-major [c][q], 3.2 MB
__device__ __half w_h[NN * NQ];     // per-pixel kernels, [n][q], fp16, 19.7 MB

// ---------------- packed f32x2 helpers ----------------
__device__ __forceinline__ unsigned long long ffma2(unsigned long long a,
                                                    unsigned long long b,
                                                    unsigned long long c) {
    unsigned long long d;
    asm("fma.rn.f32x2 %0, %1, %2, %3;" : "=l"(d) : "l"(a), "l"(b), "l"(c));
    return d;
}
__device__ __forceinline__ float2 u2f(unsigned long long v) {
    float2 r;
    asm("mov.b64 {%0,%1}, %2;" : "=f"(r.x), "=f"(r.y) : "l"(v));
    return r;
}
__device__ __forceinline__ unsigned long long f2u(float x, float y) {
    unsigned long long v;
    asm("mov.b64 %0, {%1,%2};" : "=l"(v) : "f"(x), "f"(y));
    return v;
}
__device__ __forceinline__ unsigned h2_as_u(__half2 h) {
    unsigned u;
    asm("mov.b32 %0, %1;" : "=r"(u) : "r"(*(unsigned*)&h));
    return u;
}

// =====================================================================
// Kernel 1 (GEMM form): t[o][q] = relu(scale[o]*(W1[o][:].x[:][q]) + shift[o])
// M=64 (split 2x32), N=12544, K=256 (8 chunks of 32 via smem).
// Grid (98, 2), 256 threads. CTA tile 32o x 128q; thread tile 8o x 2q.
// Per c-step: LDS.64 (x, 2q) + 2x broadcast LDS.128 (W1, 8o) + 8 FFMA2.
// smem 21.5 KB, ~60 regs -> 4 CTAs/SM resident.
// =====================================================================
#define K1_QT 128
#define K1_OT 32
#define K1_KC 32
#define XS_STRIDE  132   // floats (128 + 4 pad)
#define W1S_STRIDE 36    // floats (32 + 4 pad)

extern "C" __global__ void __launch_bounds__(256)
k1_gemm(const float* __restrict__ x, const float* __restrict__ W1,
        const float* __restrict__ b1, const float* __restrict__ gamma,
        const float* __restrict__ beta, const float* __restrict__ mean,
        const float* __restrict__ var)
{
    extern __shared__ float sm1[];
    float* xs  = sm1;                          // [32][132]
    float* w1s = sm1 + K1_KC * XS_STRIDE;      // [32][36]
    float* sc  = w1s + K1_KC * W1S_STRIDE;     // [32]
    float* sh  = sc + K1_OT;                   // [32]

    int tid = threadIdx.x;
    int q0  = blockIdx.x * K1_QT;
    int ot  = blockIdx.y * K1_OT;

    if (tid < K1_OT) {
        int o = ot + tid;
        float s = gamma[o] * rsqrtf(var[o] + 1e-5f);
        sc[tid] = s;
        sh[tid] = (b1[o] - mean[o]) * s + beta[o];
    }

    int qs = tid & 63;       // 64 q-slots x 2q
    int os = tid >> 6;       // 4 o-slots x 8o
    int o0l = os * 8;        // local o base

    unsigned long long acc[4][2];   // [o-pair][q]
    #pragma unroll
    for (int i = 0; i < 4; i++) { acc[i][0] = 0ull; acc[i][1] = 0ull; }

    for (int chunk = 0; chunk < CC / K1_KC; chunk++) {
        int c0 = chunk * K1_KC;
        // x tile [32c][128q] as float4; batch-crossing handled per float4
        #pragma unroll
        for (int k = 0; k < 4; k++) {
            int li = tid + k * 256;          // 0..1023 float4 slots
            int c  = li >> 5;
            int q4 = li & 31;
            int qg = q0 + q4 * 4;
            int b  = qg / NPIX;
            int hw = qg - b * NPIX;
            float4 v = *(const float4*)(x + ((size_t)(b * CC + c0 + c)) * NPIX + hw);
            *(float4*)(xs + c * XS_STRIDE + q4 * 4) = v;
        }
        // W1 tile transposed: w1s[c][o_loc]
        #pragma unroll
        for (int k = 0; k < 4; k++) {
            int li = tid + k * 256;          // 0..1023
            int c  = li & 31;
            int ol = li >> 5;
            w1s[c * W1S_STRIDE + ol] = W1[(size_t)(ot + ol) * CC + c0 + c];
        }
        __syncthreads();

        #pragma unroll
        for (int c = 0; c < K1_KC; c++) {
            float2 tq = *(const float2*)(xs + c * XS_STRIDE + qs * 2);
            float4 wa = *(const float4*)(w1s + c * W1S_STRIDE + o0l);
            float4 wb = *(const float4*)(w1s + c * W1S_STRIDE + o0l + 4);
            unsigned long long t0  = f2u(tq.x, tq.x);
            unsigned long long t1  = f2u(tq.y, tq.y);
            unsigned long long w01 = f2u(wa.x, wa.y);
            unsigned long long w23 = f2u(wa.z, wa.w);
            unsigned long long w45 = f2u(wb.x, wb.y);
            unsigned long long w67 = f2u(wb.z, wb.w);
            acc[0][0] = ffma2(w01, t0, acc[0][0]);
            acc[0][1] = ffma2(w01, t1, acc[0][1]);
            acc[1][0] = ffma2(w23, t0, acc[1][0]);
            acc[1][1] = ffma2(w23, t1, acc[1][1]);
            acc[2][0] = ffma2(w45, t0, acc[2][0]);
            acc[2][1] = ffma2(w45, t1, acc[2][1]);
            acc[3][0] = ffma2(w67, t0, acc[3][0]);
            acc[3][1] = ffma2(w67, t1, acc[3][1]);
        }
        __syncthreads();
    }

    // epilogue: BN + ReLU, store t_lin[o][q] as float2 per o-row
    int q = q0 + qs * 2;
    #pragma unroll
    for (int op = 0; op < 4; op++) {
        int la = o0l + 2 * op;       // local o of pair-low
        int lb = la + 1;
        float2 v0 = u2f(acc[op][0]); // (o_a@q, o_b@q)
        float2 v1 = u2f(acc[op][1]); // (o_a@q+1, o_b@q+1)
        float sa = sc[la], ha = sh[la];
        float sb = sc[lb], hb = sh[lb];
        float ra0 = fmaxf(v0.x * sa + ha, 0.f);
        float ra1 = fmaxf(v1.x * sa + ha, 0.f);
        float rb0 = fmaxf(v0.y * sb + hb, 0.f);
        float rb1 = fmaxf(v1.y * sb + hb, 0.f);
        *(float2*)(t_lin + (size_t)(ot + la) * NQ + q) = make_float2(ra0, ra1);
        *(float2*)(t_lin + (size_t)(ot + lb) * NQ + q) = make_float2(rb0, rb1);
    }
}

// =====================================================================
// Kernel 2: w-gen GEMM. C[n][q] = sum_c W2[n][c] * t[c][q] + b2[n].
// Grid (98 q-tiles, 13 n-tiles), 256 threads.
// CTA tile 64n x 128q; thread tile 8n x 4q (f32x2 over n-pairs).
// =====================================================================
#define QT 128
#define NT 64
#define TS_STRIDE  132
#define W2T_STRIDE 68

extern "C" __global__ void __launch_bounds__(256)
k2_wgen(const float* __restrict__ W2, const float* __restrict__ b2)
{
    extern __shared__ float smg[];
    float* ts  = smg;                        // [64][132]
    float* w2T = smg + 64 * TS_STRIDE;       // [64][68]

    int tid = threadIdx.x;
    int q0  = blockIdx.x * QT;
    int nb  = blockIdx.y * NT;

    #pragma unroll
    for (int k = 0; k < 8; k++) {
        int li = tid + k * 256;
        int c  = li >> 5;
        int q4 = li & 31;
        float4 v = *(const float4*)(t_lin + (size_t)c * NQ + q0 + q4 * 4);
        *(float4*)(ts + c * TS_STRIDE + q4 * 4) = v;
    }
    #pragma unroll
    for (int k = 0; k < 16; k++) {
        int li    = tid + k * 256;
        int n_loc = li >> 6;
        int c     = li & 63;
        int n     = nb + n_loc;
        float v   = (n < NN) ? W2[(size_t)n * CR + c] : 0.f;
        w2T[c * W2T_STRIDE + n_loc] = v;
    }
    __syncthreads();

    int qs = tid & 31;
    int ns = tid >> 5;
    int n0 = ns * 8;

    unsigned long long acc[4][4];
    #pragma unroll
    for (int i = 0; i < 4; i++)
        #pragma unroll
        for (int j = 0; j < 4; j++) acc[i][j] = 0ull;

    #pragma unroll 4
    for (int c = 0; c < CR; c++) {
        float4 tq = *(const float4*)(ts + c * TS_STRIDE + qs * 4);
        float4 wa = *(const float4*)(w2T + c * W2T_STRIDE + n0);
        float4 wb = *(const float4*)(w2T + c * W2T_STRIDE + n0 + 4);
        unsigned long long t0 = f2u(tq.x, tq.x), t1 = f2u(tq.y, tq.y);
        unsigned long long t2 = f2u(tq.z, tq.z), t3 = f2u(tq.w, tq.w);
        unsigned long long w01 = f2u(wa.x, wa.y), w23 = f2u(wa.z, wa.w);
        unsigned long long w45 = f2u(wb.x, wb.y), w67 = f2u(wb.z, wb.w);
        acc[0][0] = ffma2(w01, t0, acc[0][0]);
        acc[0][1] = ffma2(w01, t1, acc[0][1]);
        acc[0][2] = ffma2(w01, t2, acc[0][2]);
        acc[0][3] = ffma2(w01, t3, acc[0][3]);
        acc[1][0] = ffma2(w23, t0, acc[1][0]);
        acc[1][1] = ffma2(w23, t1, acc[1][1]);
        acc[1][2] = ffma2(w23, t2, acc[1][2]);
        acc[1][3] = ffma2(w23, t3, acc[1][3]);
        acc[2][0] = ffma2(w45, t0, acc[2][0]);
        acc[2][1] = ffma2(w45, t1, acc[2][1]);
        acc[2][2] = ffma2(w45, t2, acc[2][2]);
        acc[2][3] = ffma2(w45, t3, acc[2][3]);
        acc[3][0] = ffma2(w67, t0, acc[3][0]);
        acc[3][1] = ffma2(w67, t1, acc[3][1]);
        acc[3][2] = ffma2(w67, t2, acc[3][2]);
        acc[3][3] = ffma2(w67, t3, acc[3][3]);
    }

    #pragma unroll
    for (int np = 0; np < 4; np++) {
        int n_a = nb + n0 + 2 * np;
        int n_b = n_a + 1;
        float ba = (n_a < NN) ? b2[n_a] : 0.f;
        float bb = (n_b < NN) ? b2[n_b] : 0.f;
        float2 v0 = u2f(acc[np][0]), v1 = u2f(acc[np][1]);
        float2 v2 = u2f(acc[np][2]), v3 = u2f(acc[np][3]);
        if (n_a < NN) {
            __half2 h01 = __floats2half2_rn(v0.x + ba, v1.x + ba);
            __half2 h23 = __floats2half2_rn(v2.x + ba, v3.x + ba);
            unsigned long long pk =
                ((unsigned long long)h2_as_u(h23) << 32) | h2_as_u(h01);
            *(unsigned long long*)(w_h + (size_t)n_a * NQ + q0 + qs * 4) = pk;
        }
        if (n_b < NN) {
            __half2 h01 = __floats2half2_rn(v0.y + bb, v1.y + bb);
            __half2 h23 = __floats2half2_rn(v2.y + bb, v3.y + bb);
            unsigned long long pk =
                ((unsigned long long)h2_as_u(h23) << 32) | h2_as_u(h01);
            *(unsigned long long*)(w_h + (size_t)n_b * NQ + q0 + qs * 4) = pk;
        }
    }
}

// =====================================================================
// Kernel 3: involution. Grid (7, 16, 4), 224 threads. CTA = 8 rows x 56.
// Thread owns 2 vertically adjacent pixels, reads weights from w_h
// (coalesced across lanes), x from smem channel-pair tile.
// =====================================================================
#define XT_W 62
#define XT_H 14
#define XT_CH (XT_H * XT_W)

extern "C" __global__ void __launch_bounds__(224)
k3_inv(const float* __restrict__ x, float* __restrict__ out)
{
    extern __shared__ float sm3[];
    float2* xs2 = (float2*)sm3;              // [8][14][62] float2 = 55.5 KB

    int tid = threadIdx.x;
    int r0  = blockIdx.x * 8;
    int g   = blockIdx.y;
    int b   = blockIdx.z;

    const float* xg = x + (size_t)((b * GG + g) * CGC) * NPIX;
    for (int i = tid; i < 8 * XT_CH; i += 224) {
        int cp  = i / XT_CH;
        int rem = i - cp * XT_CH;
        int ri  = rem / XT_W;
        int ci  = rem - ri * XT_W;
        int gr  = r0 - 3 + ri;
        int gc  = ci - 3;
        float v0 = 0.f, v1 = 0.f;
        if ((unsigned)gr < HH && (unsigned)gc < WW) {
            int off = gr * WW + gc;
            v0 = xg[cp * NPIX + off];
            v1 = xg[(cp + 8) * NPIX + off];
        }
        xs2[i] = make_float2(v0, v1);
    }
    __syncthreads();

    int rl = tid / 56;
    int cl = tid - rl * 56;
    int rA = r0 + 2 * rl;
    int qA = b * NPIX + rA * WW + cl;

    const __half* wg = w_h + (size_t)(g * 49) * NQ + qA;

    unsigned long long oA[8], oB[8];
    #pragma unroll
    for (int cp = 0; cp < 8; cp++) { oA[cp] = 0ull; oB[cp] = 0ull; }

    const float2* xb0 = xs2 + (2 * rl) * XT_W + cl;

    #pragma unroll
    for (int t = 0; t < 8; t++) {
        unsigned long long wa2[7], wb2[7];
        if (t < 7) {
            #pragma unroll
            for (int j = 0; j < 7; j++) {
                float w = __half2float(wg[(size_t)(t * 7 + j) * NQ]);
                wa2[j] = f2u(w, w);
            }
        }
        if (t >= 1) {
            #pragma unroll
            for (int j = 0; j < 7; j++) {
                float w = __half2float(wg[(size_t)((t - 1) * 7 + j) * NQ + WW]);
                wb2[j] = f2u(w, w);
            }
        }
        const float2* xr = xb0 + t * XT_W;
        #pragma unroll
        for (int j = 0; j < 7; j++) {
            #pragma unroll
            for (int cp = 0; cp < 8; cp++) {
                unsigned long long xv =
                    *(const unsigned long long*)(xr + cp * XT_CH + j);
                if (t < 7)  oA[cp] = ffma2(xv, wa2[j], oA[cp]);
                if (t >= 1) oB[cp] = ffma2(xv, wb2[j], oB[cp]);
            }
        }
    }

    float* op = out + (size_t)(b * CC + g * CGC) * NPIX + rA * WW + cl;
    #pragma unroll
    for (int cp = 0; cp < 8; cp++) {
        float2 vA = u2f(oA[cp]);
        float2 vB = u2f(oB[cp]);
        op[cp * NPIX]            = vA.x;
        op[(cp + 8) * NPIX]      = vA.y;
        op[cp * NPIX + WW]       = vB.x;
        op[(cp + 8) * NPIX + WW] = vB.y;
    }
}

// =====================================================================
// Launch
// =====================================================================
extern "C" void kernel_launch(void* const* d_in, const int* in_sizes, int n_in,
                              void* d_out, int out_size) {
    const float* x     = (const float*)d_in[0];
    const float* W1    = (const float*)d_in[1];
    const float* b1    = (const float*)d_in[2];
    const float* gamma = (const float*)d_in[3];
    const float* beta  = (const float*)d_in[4];
    const float* mean  = (const float*)d_in[5];
    const float* var   = (const float*)d_in[6];
    const float* W2    = (const float*)d_in[7];
    const float* b2    = (const float*)d_in[8];
    float* out = (float*)d_out;

    const int smem1 = (K1_KC * XS_STRIDE + K1_KC * W1S_STRIDE + 2 * K1_OT)
                      * sizeof(float);                                   // ~21.8 KB
    const int smem2 = (64 * TS_STRIDE + 64 * W2T_STRIDE) * sizeof(float); // 51.2 KB
    const int smem3 = 8 * XT_CH * sizeof(float2);                         // 55.5 KB

    (void)cudaFuncSetAttribute(k1_gemm, cudaFuncAttributeMaxDynamicSharedMemorySize, smem1);
    (void)cudaFuncSetAttribute(k2_wgen, cudaFuncAttributeMaxDynamicSharedMemorySize, smem2);
    (void)cudaFuncSetAttribute(k3_inv,  cudaFuncAttributeMaxDynamicSharedMemorySize, smem3);

    k1_gemm<<<dim3(NQ / K1_QT, CR / K1_OT), 256, smem1>>>(x, W1, b1, gamma, beta, mean, var);
    k2_wgen<<<dim3(NQ / QT, (NN + NT - 1) / NT), 256, smem2>>>(W2, b2);
    k3_inv<<<dim3(HH / 8, GG, BB), 224, smem3>>>(x, out);
}

// round 14
// speedup vs baseline: 1.6795x; 1.3239x over previous
#include <cuda_runtime.h>
#include <cuda_fp16.h>
#include <cstdint>

// Problem constants
#define CC   256
#define CR   64
#define HH   56
#define WW   56
#define BB   4
#define GG   16
#define CGC  16
#define KK   7
#define NPIX (HH*WW)     // 3136
#define NQ   (BB*NPIX)   // 12544
#define NN   (GG*KK*KK)  // 784

// Intermediates
__device__ __half t_h[NQ * CR];            // t fp16, [q][64] plain
__device__ __half w_h[(size_t)NN * NQ];    // per-pixel kernels fp16, [n][q]

// ---------------- packed f32x2 helpers ----------------
__device__ __forceinline__ unsigned long long ffma2(unsigned long long a,
                                                    unsigned long long b,
                                                    unsigned long long c) {
    unsigned long long d;
    asm("fma.rn.f32x2 %0, %1, %2, %3;" : "=l"(d) : "l"(a), "l"(b), "l"(c));
    return d;
}
__device__ __forceinline__ float2 u2f(unsigned long long v) {
    float2 r;
    asm("mov.b64 {%0,%1}, %2;" : "=f"(r.x), "=f"(r.y) : "l"(v));
    return r;
}
__device__ __forceinline__ unsigned long long f2u(float x, float y) {
    unsigned long long v;
    asm("mov.b64 %0, {%1,%2};" : "=l"(v) : "f"(x), "f"(y));
    return v;
}
__device__ __forceinline__ unsigned h2_as_u(__half2 h) {
    unsigned u;
    asm("mov.b32 %0, %1;" : "=r"(u) : "r"(*(unsigned*)&h));
    return u;
}

// m16n8k16 fp16 MMA, fp32 accum, A row-major, B col-major.
__device__ __forceinline__ void mma16816(float* c, const uint32_t* a,
                                         const uint32_t* b) {
    asm volatile(
        "mma.sync.aligned.m16n8k16.row.col.f32.f16.f16.f32 "
        "{%0,%1,%2,%3}, {%4,%5,%6,%7}, {%8,%9}, {%0,%1,%2,%3};"
        : "+f"(c[0]), "+f"(c[1]), "+f"(c[2]), "+f"(c[3])
        : "r"(a[0]), "r"(a[1]), "r"(a[2]), "r"(a[3]), "r"(b[0]), "r"(b[1]));
}

// =====================================================================
// Kernel 1 (scalar GEMM): t[o][q] = relu(scale*(W1.x) + shift)
// Grid (98, 2), 256 threads. CTA tile 32o x 128q; thread tile 8o x 2q.
// Epilogue stores t_h fp16 [q][64] (plain).
// =====================================================================
#define K1_QT 128
#define K1_OT 32
#define K1_KC 32
#define XS_STRIDE  132
#define W1S_STRIDE 36

extern "C" __global__ void __launch_bounds__(256)
k1_gemm(const float* __restrict__ x, const float* __restrict__ W1,
        const float* __restrict__ b1, const float* __restrict__ gamma,
        const float* __restrict__ beta, const float* __restrict__ mean,
        const float* __restrict__ var)
{
    extern __shared__ float sm1[];
    float* xs  = sm1;                          // [32][132]
    float* w1s = sm1 + K1_KC * XS_STRIDE;      // [32][36]
    float* sc  = w1s + K1_KC * W1S_STRIDE;     // [32]
    float* sh  = sc + K1_OT;                   // [32]

    int tid = threadIdx.x;
    int q0  = blockIdx.x * K1_QT;
    int ot  = blockIdx.y * K1_OT;

    if (tid < K1_OT) {
        int o = ot + tid;
        float s = gamma[o] * rsqrtf(var[o] + 1e-5f);
        sc[tid] = s;
        sh[tid] = (b1[o] - mean[o]) * s + beta[o];
    }

    int qs = tid & 63;
    int os = tid >> 6;
    int o0l = os * 8;

    unsigned long long acc[4][2];
    #pragma unroll
    for (int i = 0; i < 4; i++) { acc[i][0] = 0ull; acc[i][1] = 0ull; }

    for (int chunk = 0; chunk < CC / K1_KC; chunk++) {
        int c0 = chunk * K1_KC;
        #pragma unroll
        for (int k = 0; k < 4; k++) {
            int li = tid + k * 256;
            int c  = li >> 5;
            int q4 = li & 31;
            int qg = q0 + q4 * 4;
            int b  = qg / NPIX;
            int hw = qg - b * NPIX;
            float4 v = *(const float4*)(x + ((size_t)(b * CC + c0 + c)) * NPIX + hw);
            *(float4*)(xs + c * XS_STRIDE + q4 * 4) = v;
        }
        #pragma unroll
        for (int k = 0; k < 4; k++) {
            int li = tid + k * 256;
            int c  = li & 31;
            int ol = li >> 5;
            w1s[c * W1S_STRIDE + ol] = W1[(size_t)(ot + ol) * CC + c0 + c];
        }
        __syncthreads();

        #pragma unroll
        for (int c = 0; c < K1_KC; c++) {
            float2 tq = *(const float2*)(xs + c * XS_STRIDE + qs * 2);
            float4 wa = *(const float4*)(w1s + c * W1S_STRIDE + o0l);
            float4 wb = *(const float4*)(w1s + c * W1S_STRIDE + o0l + 4);
            unsigned long long t0  = f2u(tq.x, tq.x);
            unsigned long long t1  = f2u(tq.y, tq.y);
            unsigned long long w01 = f2u(wa.x, wa.y);
            unsigned long long w23 = f2u(wa.z, wa.w);
            unsigned long long w45 = f2u(wb.x, wb.y);
            unsigned long long w67 = f2u(wb.z, wb.w);
            acc[0][0] = ffma2(w01, t0, acc[0][0]);
            acc[0][1] = ffma2(w01, t1, acc[0][1]);
            acc[1][0] = ffma2(w23, t0, acc[1][0]);
            acc[1][1] = ffma2(w23, t1, acc[1][1]);
            acc[2][0] = ffma2(w45, t0, acc[2][0]);
            acc[2][1] = ffma2(w45, t1, acc[2][1]);
            acc[3][0] = ffma2(w67, t0, acc[3][0]);
            acc[3][1] = ffma2(w67, t1, acc[3][1]);
        }
        __syncthreads();
    }

    // epilogue: BN + ReLU -> t_h fp16 [q][64]
    int q = q0 + qs * 2;
    #pragma unroll
    for (int op = 0; op < 4; op++) {
        int la = o0l + 2 * op;
        int lb = la + 1;
        float2 v0 = u2f(acc[op][0]);   // (o_a@q, o_b@q)
        float2 v1 = u2f(acc[op][1]);   // (o_a@q+1, o_b@q+1)
        float sa = sc[la], ha = sh[la];
        float sb = sc[lb], hb = sh[lb];
        int o = ot + la;               // even
        __half2 hq0 = __floats2half2_rn(fmaxf(v0.x * sa + ha, 0.f),
                                        fmaxf(v0.y * sb + hb, 0.f));
        __half2 hq1 = __floats2half2_rn(fmaxf(v1.x * sa + ha, 0.f),
                                        fmaxf(v1.y * sb + hb, 0.f));
        *(__half2*)(t_h + (size_t)q * CR + o)       = hq0;
        *(__half2*)(t_h + (size_t)(q + 1) * CR + o) = hq1;
    }
}

// =====================================================================
// Kernel 2 (HMMA): w[n][q] = W2[n][:].t[:][q] + b2[n]
// Grid (98 q-tiles, 13 n-tiles), 256 threads (8 warps: 2n x 4q).
// CTA tile 64n x 128q, warp tile 32n x 32q, K=64 staged once in smem.
// A = W2 fp16 [64][72], B = t_h fp16 [128][72] (stride 72 halfs = 36
// banks -> fragment LDS conflict-free). mma.sync m16n8k16 row.col.
// =====================================================================
#define AK 72

extern "C" __global__ void __launch_bounds__(256)
k2_mma(const float* __restrict__ W2, const float* __restrict__ b2)
{
    __shared__ __half As[64][AK];      // 9.2 KB
    __shared__ __half Bs[128][AK];     // 18.4 KB

    int tid = threadIdx.x;
    int q0  = blockIdx.x * 128;
    int nb  = blockIdx.y * 64;

    // A tile: W2 fp32 -> fp16. 64 rows x 32 half2.
    #pragma unroll
    for (int it = 0; it < 8; it++) {
        int i   = tid + it * 256;      // 0..2047
        int row = i >> 5;
        int cp  = i & 31;
        int n   = nb + row;
        float2 v = (n < NN) ? *(const float2*)(W2 + (size_t)n * CR + cp * 2)
                            : make_float2(0.f, 0.f);
        *(__half2*)&As[row][cp * 2] = __floats2half2_rn(v.x, v.y);
    }
    // B tile: t_h rows q0..q0+127, 16B chunks.
    #pragma unroll
    for (int it = 0; it < 4; it++) {
        int i   = tid + it * 256;      // 0..1023
        int row = i >> 3;
        int u   = i & 7;
        uint4 v = *(const uint4*)(t_h + (size_t)(q0 + row) * CR + u * 8);
        *(uint4*)&Bs[row][u * 8] = v;
    }
    __syncthreads();

    int wid  = tid >> 5;
    int lane = tid & 31;
    int grp  = lane >> 2;       // 0..7
    int tg   = lane & 3;        // 0..3
    int wn   = (wid & 1) * 32;  // warp n offset in CTA tile
    int wq   = (wid >> 1) * 32; // warp q offset

    float acc[2][4][4];
    #pragma unroll
    for (int mt = 0; mt < 2; mt++)
        #pragma unroll
        for (int nt = 0; nt < 4; nt++)
            #pragma unroll
            for (int i = 0; i < 4; i++) acc[mt][nt][i] = 0.f;

    #pragma unroll
    for (int ks = 0; ks < 4; ks++) {
        int k0 = ks * 16;
        int ca = k0 + 2 * tg;
        uint32_t a[2][4];
        #pragma unroll
        for (int mt = 0; mt < 2; mt++) {
            int r = wn + mt * 16 + grp;
            a[mt][0] = *(const uint32_t*)&As[r][ca];
            a[mt][1] = *(const uint32_t*)&As[r + 8][ca];
            a[mt][2] = *(const uint32_t*)&As[r][ca + 8];
            a[mt][3] = *(const uint32_t*)&As[r + 8][ca + 8];
        }
        uint32_t bfr[4][2];
        #pragma unroll
        for (int nt = 0; nt < 4; nt++) {
            int r = wq + nt * 8 + grp;
            bfr[nt][0] = *(const uint32_t*)&Bs[r][ca];
            bfr[nt][1] = *(const uint32_t*)&Bs[r][ca + 8];
        }
        #pragma unroll
        for (int mt = 0; mt < 2; mt++)
            #pragma unroll
            for (int nt = 0; nt < 4; nt++)
                mma16816(acc[mt][nt], a[mt], bfr[nt]);
    }

    // epilogue: +bias, fp16, store w_h[n][q]
    #pragma unroll
    for (int mt = 0; mt < 2; mt++) {
        int n_lo = nb + wn + mt * 16 + grp;
        int n_hi = n_lo + 8;
        float b_lo = (n_lo < NN) ? b2[n_lo] : 0.f;
        float b_hi = (n_hi < NN) ? b2[n_hi] : 0.f;
        #pragma unroll
        for (int nt = 0; nt < 4; nt++) {
            int q = q0 + wq + nt * 8 + 2 * tg;
            float* c = acc[mt][nt];
            if (n_lo < NN)
                *(__half2*)(w_h + (size_t)n_lo * NQ + q) =
                    __floats2half2_rn(c[0] + b_lo, c[1] + b_lo);
            if (n_hi < NN)
                *(__half2*)(w_h + (size_t)n_hi * NQ + q) =
                    __floats2half2_rn(c[2] + b_hi, c[3] + b_hi);
        }
    }
}

// =====================================================================
// Kernel 3: involution. Grid (7, 16, 4), 224 threads. CTA = 8 rows x 56.
// =====================================================================
#define XT_W 62
#define XT_H 14
#define XT_CH (XT_H * XT_W)

extern "C" __global__ void __launch_bounds__(224)
k3_inv(const float* __restrict__ x, float* __restrict__ out)
{
    extern __shared__ float sm3[];
    float2* xs2 = (float2*)sm3;              // [8][14][62] float2 = 55.5 KB

    int tid = threadIdx.x;
    int r0  = blockIdx.x * 8;
    int g   = blockIdx.y;
    int b   = blockIdx.z;

    const float* xg = x + (size_t)((b * GG + g) * CGC) * NPIX;
    for (int i = tid; i < 8 * XT_CH; i += 224) {
        int cp  = i / XT_CH;
        int rem = i - cp * XT_CH;
        int ri  = rem / XT_W;
        int ci  = rem - ri * XT_W;
        int gr  = r0 - 3 + ri;
        int gc  = ci - 3;
        float v0 = 0.f, v1 = 0.f;
        if ((unsigned)gr < HH && (unsigned)gc < WW) {
            int off = gr * WW + gc;
            v0 = xg[cp * NPIX + off];
            v1 = xg[(cp + 8) * NPIX + off];
        }
        xs2[i] = make_float2(v0, v1);
    }
    __syncthreads();

    int rl = tid / 56;
    int cl = tid - rl * 56;
    int rA = r0 + 2 * rl;
    int qA = b * NPIX + rA * WW + cl;

    const __half* wg = w_h + (size_t)(g * 49) * NQ + qA;

    unsigned long long oA[8], oB[8];
    #pragma unroll
    for (int cp = 0; cp < 8; cp++) { oA[cp] = 0ull; oB[cp] = 0ull; }

    const float2* xb0 = xs2 + (2 * rl) * XT_W + cl;

    #pragma unroll
    for (int t = 0; t < 8; t++) {
        unsigned long long wa2[7], wb2[7];
        if (t < 7) {
            #pragma unroll
            for (int j = 0; j < 7; j++) {
                float w = __half2float(wg[(size_t)(t * 7 + j) * NQ]);
                wa2[j] = f2u(w, w);
            }
        }
        if (t >= 1) {
            #pragma unroll
            for (int j = 0; j < 7; j++) {
                float w = __half2float(wg[(size_t)((t - 1) * 7 + j) * NQ + WW]);
                wb2[j] = f2u(w, w);
            }
        }
        const float2* xr = xb0 + t * XT_W;
        #pragma unroll
        for (int j = 0; j < 7; j++) {
            #pragma unroll
            for (int cp = 0; cp < 8; cp++) {
                unsigned long long xv =
                    *(const unsigned long long*)(xr + cp * XT_CH + j);
                if (t < 7)  oA[cp] = ffma2(xv, wa2[j], oA[cp]);
                if (t >= 1) oB[cp] = ffma2(xv, wb2[j], oB[cp]);
            }
        }
    }

    float* op = out + (size_t)(b * CC + g * CGC) * NPIX + rA * WW + cl;
    #pragma unroll
    for (int cp = 0; cp < 8; cp++) {
        float2 vA = u2f(oA[cp]);
        float2 vB = u2f(oB[cp]);
        op[cp * NPIX]            = vA.x;
        op[(cp + 8) * NPIX]      = vA.y;
        op[cp * NPIX + WW]       = vB.x;
        op[(cp + 8) * NPIX + WW] = vB.y;
    }
}

// =====================================================================
// Launch
// =====================================================================
extern "C" void kernel_launch(void* const* d_in, const int* in_sizes, int n_in,
                              void* d_out, int out_size) {
    const float* x     = (const float*)d_in[0];
    const float* W1    = (const float*)d_in[1];
    const float* b1    = (const float*)d_in[2];
    const float* gamma = (const float*)d_in[3];
    const float* beta  = (const float*)d_in[4];
    const float* mean  = (const float*)d_in[5];
    const float* var   = (const float*)d_in[6];
    const float* W2    = (const float*)d_in[7];
    const float* b2    = (const float*)d_in[8];
    float* out = (float*)d_out;

    const int smem1 = (K1_KC * XS_STRIDE + K1_KC * W1S_STRIDE + 2 * K1_OT)
                      * sizeof(float);                 // ~21.8 KB
    const int smem3 = 8 * XT_CH * sizeof(float2);      // 55.5 KB

    (void)cudaFuncSetAttribute(k1_gemm, cudaFuncAttributeMaxDynamicSharedMemorySize, smem1);
    (void)cudaFuncSetAttribute(k3_inv,  cudaFuncAttributeMaxDynamicSharedMemorySize, smem3);

    k1_gemm<<<dim3(NQ / K1_QT, CR / K1_OT), 256, smem1>>>(x, W1, b1, gamma, beta, mean, var);
    k2_mma<<<dim3(NQ / 128, (NN + 63) / 64), 256>>>(W2, b2);
    k3_inv<<<dim3(HH / 8, GG, BB), 224, smem3>>>(x, out);
}

// round 15
// speedup vs baseline: 1.8519x; 1.1026x over previous
#include <cuda_runtime.h>
#include <cuda_fp16.h>
#include <cstdint>

// Problem constants
#define CC   256
#define CR   64
#define HH   56
#define WW   56
#define BB   4
#define GG   16
#define CGC  16
#define KK   7
#define NPIX (HH*WW)     // 3136
#define NQ   (BB*NPIX)   // 12544
#define NN   (GG*KK*KK)  // 784

// Intermediates
__device__ __half t_h[NQ * CR];            // t fp16, [q][64] plain
__device__ __half w_h[(size_t)NN * NQ];    // per-pixel kernels fp16, [n][q]

// ---------------- packed f32x2 helpers ----------------
__device__ __forceinline__ unsigned long long ffma2(unsigned long long a,
                                                    unsigned long long b,
                                                    unsigned long long c) {
    unsigned long long d;
    asm("fma.rn.f32x2 %0, %1, %2, %3;" : "=l"(d) : "l"(a), "l"(b), "l"(c));
    return d;
}
__device__ __forceinline__ float2 u2f(unsigned long long v) {
    float2 r;
    asm("mov.b64 {%0,%1}, %2;" : "=f"(r.x), "=f"(r.y) : "l"(v));
    return r;
}
__device__ __forceinline__ unsigned long long f2u(float x, float y) {
    unsigned long long v;
    asm("mov.b64 %0, {%1,%2};" : "=l"(v) : "f"(x), "f"(y));
    return v;
}
__device__ __forceinline__ uint32_t smem_u32(const void* p) {
    uint32_t a;
    asm("{ .reg .u64 t; cvta.to.shared.u64 t, %1; cvt.u32.u64 %0, t; }"
        : "=r"(a) : "l"(p));
    return a;
}
__device__ __forceinline__ void cp16(uint32_t saddr, const void* g) {
    asm volatile("cp.async.ca.shared.global [%0], [%1], 16;"
                 :: "r"(saddr), "l"(g));
}
#define CP_COMMIT() asm volatile("cp.async.commit_group;" ::: "memory")
#define CP_WAIT(n)  asm volatile("cp.async.wait_group %0;" :: "n"(n) : "memory")

// m16n8k16 fp16 MMA, fp32 accum, A row-major, B col-major.
__device__ __forceinline__ void mma16816(float* c, const uint32_t* a,
                                         const uint32_t* b) {
    asm volatile(
        "mma.sync.aligned.m16n8k16.row.col.f32.f16.f16.f32 "
        "{%0,%1,%2,%3}, {%4,%5,%6,%7}, {%8,%9}, {%0,%1,%2,%3};"
        : "+f"(c[0]), "+f"(c[1]), "+f"(c[2]), "+f"(c[3])
        : "r"(a[0]), "r"(a[1]), "r"(a[2]), "r"(a[3]), "r"(b[0]), "r"(b[1]));
}

// =====================================================================
// Kernel 1: t[q][o] = relu(scale*(W1.x) + shift), fp16 out.
// Grid (196, 2) x 128 threads. CTA tile 32o x 64q; thread tile 8o x 2q.
// W1 staged once (transposed, warp-uniform broadcast reads); x chunks
// (32c x 64q) cp.async double-buffered. 64 | NPIX -> no batch crossing.
// =====================================================================
#define K1_QT 64
#define K1_OT 32
#define K1_KC 32
#define K1_NCH (CC / K1_KC)   // 8
#define XSS 68                // x smem row stride (floats)
#define W1S 36                // W1 smem row stride (floats)

extern "C" __global__ void __launch_bounds__(128)
k1_gemm(const float* __restrict__ x, const float* __restrict__ W1,
        const float* __restrict__ b1, const float* __restrict__ gamma,
        const float* __restrict__ beta, const float* __restrict__ mean,
        const float* __restrict__ var)
{
    extern __shared__ float sm1[];
    float* w1T = sm1;                       // [256][36] (c-major, o fast)
    float* xs  = sm1 + CC * W1S;            // [2][32][68]
    float* sc  = xs + 2 * K1_KC * XSS;      // [32]
    float* sh  = sc + K1_OT;                // [32]

    int tid = threadIdx.x;
    int q0  = blockIdx.x * K1_QT;
    int ot  = blockIdx.y * K1_OT;
    int b   = q0 / NPIX;
    int hw0 = q0 - b * NPIX;
    const float* xb = x + (size_t)b * CC * NPIX + hw0;
    uint32_t xs_u = smem_u32(xs);

    // issue x chunk 0 (async) first, then stage W1 while it flies
    {
        #pragma unroll
        for (int it = 0; it < 4; it++) {
            int li = tid + it * 128;       // 0..511
            int c  = li >> 4;
            int q4 = li & 15;
            cp16(xs_u + (uint32_t)(c * XSS + q4 * 4) * 4,
                 xb + (size_t)c * NPIX + q4 * 4);
        }
        CP_COMMIT();
    }

    // W1 tile transposed into smem: w1T[c][ol]
    #pragma unroll 8
    for (int it = 0; it < 64; it++) {
        int li = tid + it * 128;
        int ol = li >> 8;
        int c  = li & 255;
        w1T[c * W1S + ol] = W1[(size_t)(ot + ol) * CC + c];
    }
    if (tid < K1_OT) {
        int o = ot + tid;
        float s = gamma[o] * rsqrtf(var[o] + 1e-5f);
        sc[tid] = s;
        sh[tid] = (b1[o] - mean[o]) * s + beta[o];
    }

    int qs  = tid & 31;
    int os  = tid >> 5;       // warp id 0..3
    int o0l = os * 8;

    unsigned long long acc[4][2];   // [o-pair][q]
    #pragma unroll
    for (int i = 0; i < 4; i++) { acc[i][0] = 0ull; acc[i][1] = 0ull; }

    for (int ch = 0; ch < K1_NCH; ch++) {
        if (ch + 1 < K1_NCH) {
            uint32_t dst = xs_u + (uint32_t)(((ch + 1) & 1) * K1_KC * XSS) * 4;
            int cg0 = (ch + 1) * K1_KC;
            #pragma unroll
            for (int it = 0; it < 4; it++) {
                int li = tid + it * 128;
                int c  = li >> 4;
                int q4 = li & 15;
                cp16(dst + (uint32_t)(c * XSS + q4 * 4) * 4,
                     xb + (size_t)(cg0 + c) * NPIX + q4 * 4);
            }
            CP_COMMIT();
            CP_WAIT(1);
        } else {
            CP_WAIT(0);
        }
        __syncthreads();

        const float* xc = xs + (ch & 1) * K1_KC * XSS;
        const float* wc = w1T + (ch * K1_KC) * W1S;
        #pragma unroll
        for (int c = 0; c < K1_KC; c++) {
            float2 xq = *(const float2*)(xc + c * XSS + qs * 2);
            float4 wa = *(const float4*)(wc + c * W1S + o0l);      // uniform
            float4 wb = *(const float4*)(wc + c * W1S + o0l + 4);  // uniform
            unsigned long long t0  = f2u(xq.x, xq.x);
            unsigned long long t1  = f2u(xq.y, xq.y);
            unsigned long long w01 = f2u(wa.x, wa.y);
            unsigned long long w23 = f2u(wa.z, wa.w);
            unsigned long long w45 = f2u(wb.x, wb.y);
            unsigned long long w67 = f2u(wb.z, wb.w);
            acc[0][0] = ffma2(w01, t0, acc[0][0]);
            acc[0][1] = ffma2(w01, t1, acc[0][1]);
            acc[1][0] = ffma2(w23, t0, acc[1][0]);
            acc[1][1] = ffma2(w23, t1, acc[1][1]);
            acc[2][0] = ffma2(w45, t0, acc[2][0]);
            acc[2][1] = ffma2(w45, t1, acc[2][1]);
            acc[3][0] = ffma2(w67, t0, acc[3][0]);
            acc[3][1] = ffma2(w67, t1, acc[3][1]);
        }
        __syncthreads();
    }

    // epilogue: BN + ReLU -> t_h[q][64] fp16 (half2 over consecutive o)
    int q = q0 + qs * 2;
    #pragma unroll
    for (int op = 0; op < 4; op++) {
        int la = o0l + 2 * op;
        int lb = la + 1;
        float sa = sc[la], ha = sh[la];
        float sb = sc[lb], hb = sh[lb];
        int og = ot + la;                      // even
        float2 v0 = u2f(acc[op][0]);           // (o_la@q,   o_lb@q)
        float2 v1 = u2f(acc[op][1]);           // (o_la@q+1, o_lb@q+1)
        __half2 h0 = __floats2half2_rn(fmaxf(v0.x * sa + ha, 0.f),
                                       fmaxf(v0.y * sb + hb, 0.f));
        __half2 h1 = __floats2half2_rn(fmaxf(v1.x * sa + ha, 0.f),
                                       fmaxf(v1.y * sb + hb, 0.f));
        *(__half2*)(t_h + (size_t)q * CR + og)       = h0;
        *(__half2*)(t_h + (size_t)(q + 1) * CR + og) = h1;
    }
}

// =====================================================================
// Kernel 2 (HMMA): w[n][q] = W2[n][:].t[:][q] + b2[n]   (unchanged)
// Grid (98 q-tiles, 13 n-tiles), 256 threads (8 warps: 2n x 4q).
// =====================================================================
#define AK 72

extern "C" __global__ void __launch_bounds__(256)
k2_mma(const float* __restrict__ W2, const float* __restrict__ b2)
{
    __shared__ __half As[64][AK];      // 9.2 KB
    __shared__ __half Bs[128][AK];     // 18.4 KB

    int tid = threadIdx.x;
    int q0  = blockIdx.x * 128;
    int nb  = blockIdx.y * 64;

    #pragma unroll
    for (int it = 0; it < 8; it++) {
        int i   = tid + it * 256;
        int row = i >> 5;
        int cp  = i & 31;
        int n   = nb + row;
        float2 v = (n < NN) ? *(const float2*)(W2 + (size_t)n * CR + cp * 2)
                            : make_float2(0.f, 0.f);
        *(__half2*)&As[row][cp * 2] = __floats2half2_rn(v.x, v.y);
    }
    #pragma unroll
    for (int it = 0; it < 4; it++) {
        int i   = tid + it * 256;
        int row = i >> 3;
        int u   = i & 7;
        uint4 v = *(const uint4*)(t_h + (size_t)(q0 + row) * CR + u * 8);
        *(uint4*)&Bs[row][u * 8] = v;
    }
    __syncthreads();

    int wid  = tid >> 5;
    int lane = tid & 31;
    int grp  = lane >> 2;
    int tg   = lane & 3;
    int wn   = (wid & 1) * 32;
    int wq   = (wid >> 1) * 32;

    float acc[2][4][4];
    #pragma unroll
    for (int mt = 0; mt < 2; mt++)
        #pragma unroll
        for (int nt = 0; nt < 4; nt++)
            #pragma unroll
            for (int i = 0; i < 4; i++) acc[mt][nt][i] = 0.f;

    #pragma unroll
    for (int ks = 0; ks < 4; ks++) {
        int ca = ks * 16 + 2 * tg;
        uint32_t a[2][4];
        #pragma unroll
        for (int mt = 0; mt < 2; mt++) {
            int r = wn + mt * 16 + grp;
            a[mt][0] = *(const uint32_t*)&As[r][ca];
            a[mt][1] = *(const uint32_t*)&As[r + 8][ca];
            a[mt][2] = *(const uint32_t*)&As[r][ca + 8];
            a[mt][3] = *(const uint32_t*)&As[r + 8][ca + 8];
        }
        uint32_t bfr[4][2];
        #pragma unroll
        for (int nt = 0; nt < 4; nt++) {
            int r = wq + nt * 8 + grp;
            bfr[nt][0] = *(const uint32_t*)&Bs[r][ca];
            bfr[nt][1] = *(const uint32_t*)&Bs[r][ca + 8];
        }
        #pragma unroll
        for (int mt = 0; mt < 2; mt++)
            #pragma unroll
            for (int nt = 0; nt < 4; nt++)
                mma16816(acc[mt][nt], a[mt], bfr[nt]);
    }

    #pragma unroll
    for (int mt = 0; mt < 2; mt++) {
        int n_lo = nb + wn + mt * 16 + grp;
        int n_hi = n_lo + 8;
        float b_lo = (n_lo < NN) ? b2[n_lo] : 0.f;
        float b_hi = (n_hi < NN) ? b2[n_hi] : 0.f;
        #pragma unroll
        for (int nt = 0; nt < 4; nt++) {
            int q = q0 + wq + nt * 8 + 2 * tg;
            float* c = acc[mt][nt];
            if (n_lo < NN)
                *(__half2*)(w_h + (size_t)n_lo * NQ + q) =
                    __floats2half2_rn(c[0] + b_lo, c[1] + b_lo);
            if (n_hi < NN)
                *(__half2*)(w_h + (size_t)n_hi * NQ + q) =
                    __floats2half2_rn(c[2] + b_hi, c[3] + b_hi);
        }
    }
}

// =====================================================================
// Kernel 3: involution (unchanged). Grid (7, 16, 4), 224 threads.
// =====================================================================
#define XT_W 62
#define XT_H 14
#define XT_CH (XT_H * XT_W)

extern "C" __global__ void __launch_bounds__(224)
k3_inv(const float* __restrict__ x, float* __restrict__ out)
{
    extern __shared__ float sm3[];
    float2* xs2 = (float2*)sm3;              // [8][14][62] float2 = 55.5 KB

    int tid = threadIdx.x;
    int r0  = blockIdx.x * 8;
    int g   = blockIdx.y;
    int b   = blockIdx.z;

    const float* xg = x + (size_t)((b * GG + g) * CGC) * NPIX;
    for (int i = tid; i < 8 * XT_CH; i += 224) {
        int cp  = i / XT_CH;
        int rem = i - cp * XT_CH;
        int ri  = rem / XT_W;
        int ci  = rem - ri * XT_W;
        int gr  = r0 - 3 + ri;
        int gc  = ci - 3;
        float v0 = 0.f, v1 = 0.f;
        if ((unsigned)gr < HH && (unsigned)gc < WW) {
            int off = gr * WW + gc;
            v0 = xg[cp * NPIX + off];
            v1 = xg[(cp + 8) * NPIX + off];
        }
        xs2[i] = make_float2(v0, v1);
    }
    __syncthreads();

    int rl = tid / 56;
    int cl = tid - rl * 56;
    int rA = r0 + 2 * rl;
    int qA = b * NPIX + rA * WW + cl;

    const __half* wg = w_h + (size_t)(g * 49) * NQ + qA;

    unsigned long long oA[8], oB[8];
    #pragma unroll
    for (int cp = 0; cp < 8; cp++) { oA[cp] = 0ull; oB[cp] = 0ull; }

    const float2* xb0 = xs2 + (2 * rl) * XT_W + cl;

    #pragma unroll
    for (int t = 0; t < 8; t++) {
        unsigned long long wa2[7], wb2[7];
        if (t < 7) {
            #pragma unroll
            for (int j = 0; j < 7; j++) {
                float w = __half2float(wg[(size_t)(t * 7 + j) * NQ]);
                wa2[j] = f2u(w, w);
            }
        }
        if (t >= 1) {
            #pragma unroll
            for (int j = 0; j < 7; j++) {
                float w = __half2float(wg[(size_t)((t - 1) * 7 + j) * NQ + WW]);
                wb2[j] = f2u(w, w);
            }
        }
        const float2* xr = xb0 + t * XT_W;
        #pragma unroll
        for (int j = 0; j < 7; j++) {
            #pragma unroll
            for (int cp = 0; cp < 8; cp++) {
                unsigned long long xv =
                    *(const unsigned long long*)(xr + cp * XT_CH + j);
                if (t < 7)  oA[cp] = ffma2(xv, wa2[j], oA[cp]);
                if (t >= 1) oB[cp] = ffma2(xv, wb2[j], oB[cp]);
            }
        }
    }

    float* op = out + (size_t)(b * CC + g * CGC) * NPIX + rA * WW + cl;
    #pragma unroll
    for (int cp = 0; cp < 8; cp++) {
        float2 vA = u2f(oA[cp]);
        float2 vB = u2f(oB[cp]);
        op[cp * NPIX]            = vA.x;
        op[(cp + 8) * NPIX]      = vA.y;
        op[cp * NPIX + WW]       = vB.x;
        op[(cp + 8) * NPIX + WW] = vB.y;
    }
}

// =====================================================================
// Launch
// =====================================================================
extern "C" void kernel_launch(void* const* d_in, const int* in_sizes, int n_in,
                              void* d_out, int out_size) {
    const float* x     = (const float*)d_in[0];
    const float* W1    = (const float*)d_in[1];
    const float* b1    = (const float*)d_in[2];
    const float* gamma = (const float*)d_in[3];
    const float* beta  = (const float*)d_in[4];
    const float* mean  = (const float*)d_in[5];
    const float* var   = (const float*)d_in[6];
    const float* W2    = (const float*)d_in[7];
    const float* b2    = (const float*)d_in[8];
    float* out = (float*)d_out;

    const int smem1 = (CC * W1S + 2 * K1_KC * XSS + 2 * K1_OT) * sizeof(float); // ~53.3 KB
    const int smem3 = 8 * XT_CH * sizeof(float2);                               // 55.5 KB

    (void)cudaFuncSetAttribute(k1_gemm, cudaFuncAttributeMaxDynamicSharedMemorySize, smem1);
    (void)cudaFuncSetAttribute(k3_inv,  cudaFuncAttributeMaxDynamicSharedMemorySize, smem3);

    k1_gemm<<<dim3(NQ / K1_QT, CR / K1_OT), 128, smem1>>>(x, W1, b1, gamma, beta, mean, var);
    k2_mma<<<dim3(NQ / 128, (NN + 63) / 64), 256>>>(W2, b2);
    k3_inv<<<dim3(HH / 8, GG, BB), 224, smem3>>>(x, out);
}